// round 12
// baseline (speedup 1.0000x reference)
#include <cuda_runtime.h>
#include <math.h>
#include <stdint.h>

#define BB 128
#define TT 256
#define HH 512
#define G4 2048  // 4*H

// ---------------- scratch (static device memory; no allocations) -------------
__device__ float    g_xproj[134217728];   // 2 dirs * 32768 * 2048 fp32 (512 MB)
__device__ float    g_hist[33554432];     // 2 dirs * 128*256*512 fp32 (128 MB)
__device__ unsigned g_apack[33554432];    // 2 packed A matrices (fragment-major) 128 MB
__device__ unsigned g_bpack[4194304];     // 4 packed Wx matrices (fragment-major) 16 MB
__device__ uint4    g_hpack[65536];       // rec h ping-pong: 2 dirs x 2 par x 16384 uint4 (1 MB)

// grid-barrier state (self-cleaning count; monotonically rising flag)
__device__ unsigned g_barcnt[2];
__device__ unsigned g_barflag[2];

// ---------------- tf32 helpers ----------------------------------------------
__device__ __forceinline__ unsigned f2tf32(float f) {
    unsigned r;
    asm("cvt.rna.tf32.f32 %0, %1;" : "=r"(r) : "f"(f));
    return r;
}

__device__ __forceinline__ void mma_tf32(float* c, const unsigned* a, const unsigned* b) {
    asm volatile(
        "mma.sync.aligned.m16n8k8.row.col.f32.tf32.tf32.f32 "
        "{%0,%1,%2,%3}, {%4,%5,%6,%7}, {%8,%9}, {%0,%1,%2,%3};"
        : "+f"(c[0]), "+f"(c[1]), "+f"(c[2]), "+f"(c[3])
        : "r"(a[0]), "r"(a[1]), "r"(a[2]), "r"(a[3]),
          "r"(b[0]), "r"(b[1]));
}

// ---------------- release/acquire primitives ---------------------------------
__device__ __forceinline__ unsigned atom_add_release(unsigned* p, unsigned v) {
    unsigned old;
    asm volatile("atom.release.gpu.global.add.u32 %0, [%1], %2;"
                 : "=r"(old) : "l"(p), "r"(v) : "memory");
    return old;
}
__device__ __forceinline__ void st_release(unsigned* p, unsigned v) {
    asm volatile("st.release.gpu.global.u32 [%0], %1;" :: "l"(p), "r"(v) : "memory");
}
__device__ __forceinline__ unsigned ld_acquire(unsigned* p) {
    unsigned v;
    asm volatile("ld.acquire.gpu.global.u32 %0, [%1];" : "=r"(v) : "l"(p) : "memory");
    return v;
}

// ---------------- operand pack kernels (unchanged) ---------------------------
__global__ __launch_bounds__(256)
void pack_a(const float* __restrict__ A, unsigned* __restrict__ Ag)
{
    const int k8  = blockIdx.x;
    const int rg  = blockIdx.y * 8 + (threadIdx.x >> 5);
    const int lane = threadIdx.x & 31;
    const int g = lane >> 2, tig = lane & 3;
    const size_t r0 = (size_t)(rg * 16 + g) * 512;
    const size_t r1 = r0 + 8 * 512;
    const int c0 = k8 * 8 + tig;
    uint4 u;
    u.x = f2tf32(A[r0 + c0]);
    u.y = f2tf32(A[r1 + c0]);
    u.z = f2tf32(A[r0 + c0 + 4]);
    u.w = f2tf32(A[r1 + c0 + 4]);
    *(uint4*)(Ag + ((size_t)k8 * 2048 + rg) * 128 + lane * 4) = u;
}

__global__ __launch_bounds__(256)
void pack_b(const float* __restrict__ Wx, unsigned* __restrict__ Bg)
{
    const int k8 = blockIdx.x;
    const int n8 = blockIdx.y * 8 + (threadIdx.x >> 5);
    const int ld = blockIdx.z;
    const int lane = threadIdx.x & 31;
    const int g = lane >> 2, tig = lane & 3;
    const float* W = Wx + (size_t)ld * 512 * 2048;
    const size_t col = (size_t)n8 * 8 + g;
    uint2 u;
    u.x = f2tf32(W[(size_t)(k8 * 8 + tig)     * 2048 + col]);
    u.y = f2tf32(W[(size_t)(k8 * 8 + tig + 4) * 2048 + col]);
    *(uint2*)(Bg + (((size_t)ld * 64 + k8) * 256 + n8) * 64 + lane * 2) = u;
}

// ---------------- zero-smem packed-fragment GEMM (unchanged) -----------------
__global__ __launch_bounds__(256)
void gemm_pk(const unsigned* __restrict__ Ag,
             const unsigned* __restrict__ Bg,
             const float* __restrict__ bias,
             float* __restrict__ C)
{
    const int tid  = threadIdx.x;
    const int wid  = tid >> 5;
    const int lane = tid & 31;
    const int g    = lane >> 2;
    const int tig  = lane & 3;
    const int wm   = wid >> 2;
    const int wn   = wid & 3;
    const long m0  = (long)blockIdx.y * 128;
    const int  n0  = blockIdx.x * 128;
    const int  rgb = blockIdx.y * 8 + wm * 4;
    const int  n8b = blockIdx.x * 16 + wn * 4;

    const uint4* __restrict__ A4 = (const uint4*)Ag;
    const uint2* __restrict__ B2 = (const uint2*)Bg;

    float acc[4][4][4];
#pragma unroll
    for (int i = 0; i < 4; i++)
#pragma unroll
        for (int j = 0; j < 4; j++)
#pragma unroll
            for (int q = 0; q < 4; q++) acc[i][j][q] = 0.f;

    uint4 av[4]; uint2 bv[4];
#pragma unroll
    for (int mt = 0; mt < 4; mt++)
        av[mt] = A4[(size_t)(rgb + mt) * 32 + lane];
#pragma unroll
    for (int nt = 0; nt < 4; nt++)
        bv[nt] = B2[(size_t)(n8b + nt) * 32 + lane];

#pragma unroll 4
    for (int k8 = 0; k8 < 64; k8++) {
        uint4 an[4]; uint2 bn[4];
        if (k8 < 63) {
            const size_t ao = (size_t)(k8 + 1) * 65536;
            const size_t bo = (size_t)(k8 + 1) * 8192;
#pragma unroll
            for (int mt = 0; mt < 4; mt++)
                an[mt] = A4[ao + (size_t)(rgb + mt) * 32 + lane];
#pragma unroll
            for (int nt = 0; nt < 4; nt++)
                bn[nt] = B2[bo + (size_t)(n8b + nt) * 32 + lane];
        }
#pragma unroll
        for (int mt = 0; mt < 4; mt++)
#pragma unroll
            for (int nt = 0; nt < 4; nt++)
                mma_tf32(acc[mt][nt], (const unsigned*)&av[mt],
                         (const unsigned*)&bv[nt]);
        if (k8 < 63) {
#pragma unroll
            for (int mt = 0; mt < 4; mt++) av[mt] = an[mt];
#pragma unroll
            for (int nt = 0; nt < 4; nt++) bv[nt] = bn[nt];
        }
    }

#pragma unroll
    for (int mt = 0; mt < 4; mt++) {
#pragma unroll
        for (int nt = 0; nt < 4; nt++) {
            long r0 = m0 + wm * 64 + mt * 16 + g;
            int cc = n0 + wn * 32 + nt * 8 + tig * 2;
            float b0 = bias[cc], b1 = bias[cc + 1];
            C[r0 * 2048 + cc]           = acc[mt][nt][0] + b0;
            C[r0 * 2048 + cc + 1]       = acc[mt][nt][1] + b1;
            C[(r0 + 8) * 2048 + cc]     = acc[mt][nt][2] + b0;
            C[(r0 + 8) * 2048 + cc + 1] = acc[mt][nt][3] + b1;
        }
    }
}

// ---------------- recurrence: 2 CTAs/SM, paired directions --------------------
// grid (64 j-tiles of 8, 2 M-halves, 2 dirs) = 256 CTAs, 256 threads, 2/SM.
// Each SM hosts one fwd and one bwd CTA: when one direction spins at its grid
// barrier, the other direction's warps use the SM. Warps: wm(4 M-groups of 16
// rows) x wjq(2 j-quads). Thread owns (r0, r0+8) x one j, all 4 gates local.
struct RecP {
    const float* xp[2];   // per dir input projections [B*T, 2048]
    const float* Wh[2];   // per dir [512, 2048]
    float*       h[2];    // per dir fp32 h base
    long bstride;
    long tstride;
};

#define REC_SMEM (64 * 2 * 128 * 4)   // Bp: [k8][wjq(2)][128 words] = 64 KB

__global__ __launch_bounds__(256, 2)
void lstm_rec(RecP p)
{
    extern __shared__ unsigned Bp[];

    const int q    = blockIdx.x;        // j-tile: j in [q*8, q*8+8)
    const int mh   = blockIdx.y;        // M half: rows [mh*64, mh*64+64)
    const int dir  = blockIdx.z;
    const int tid  = threadIdx.x;
    const int wid  = tid >> 5;
    const int lane = tid & 31;
    const int g    = lane >> 2;
    const int tig  = lane & 3;
    const int wm   = wid & 3;           // M-group within half
    const int wjq  = wid >> 2;          // j-quad 0..1

    const float* __restrict__ xp = p.xp[dir];
    const float* __restrict__ Wh = p.Wh[dir];
    float* __restrict__ hb = p.h[dir];
    const long bstride = p.bstride;
    const long tstride = p.tstride;

    // ---- pack Wh gate-interleaved fragments into smem (one-time) ----
    // frag (k8, wj, gp): n-index nn = g -> gate = gp*2 + (nn&1), jloc = nn>>1;
    // rows k8*8+tig (+4).
#pragma unroll
    for (int i = 0; i < 8; i++) {
        const int k8 = wid * 8 + i;
#pragma unroll
        for (int wj = 0; wj < 2; wj++) {
#pragma unroll
            for (int gp = 0; gp < 2; gp++) {
                const size_t col = (size_t)(gp * 2 + (g & 1)) * 512
                                 + q * 8 + wj * 4 + (g >> 1);
                unsigned v0 = f2tf32(Wh[(size_t)(k8 * 8 + tig)     * 2048 + col]);
                unsigned v1 = f2tf32(Wh[(size_t)(k8 * 8 + tig + 4) * 2048 + col]);
                Bp[(k8 * 2 + wj) * 128 + lane * 4 + gp * 2]     = v0;
                Bp[(k8 * 2 + wj) * 128 + lane * 4 + gp * 2 + 1] = v1;
            }
        }
    }
    __syncthreads();

    const int r0 = mh * 64 + wm * 16 + g;       // batch rows r0, r0+8
    const int j  = q * 8 + wjq * 4 + tig;       // this thread's hidden unit
    const int rg = mh * 4 + wm;                  // packed-h rowgroup (r0>>4)

    // packed-h bases (uint4 units): per dir 32768, per parity 16384
    uint4* hp_base = g_hpack + (size_t)dir * 32768;
    const int k8p  = j >> 3;                     // == q
    const int kbit = (j >> 2) & 1;               // == wjq
    const size_t woff = ((size_t)(k8p * 8 + rg)) * 128 + lane * 4 + kbit * 2;

    float creg[2] = {0.f, 0.f};

    for (int s = 0; s < TT; s++) {
        const int t = dir ? (TT - 1 - s) : s;

        // ---- prefetch xproj gates (consumed in epilogue; hidden under mma) ----
        float xv[4][2];
#pragma unroll
        for (int rr = 0; rr < 2; rr++) {
            const size_t xb = ((size_t)(r0 + rr * 8) * TT + t) * 2048 + j;
#pragma unroll
            for (int gt = 0; gt < 4; gt++)
                xv[gt][rr] = xp[xb + gt * 512];
        }

        float acc0[4] = {0.f, 0.f, 0.f, 0.f};   // gates i,f
        float acc1[4] = {0.f, 0.f, 0.f, 0.f};   // gates g,o

        if (s > 0) {
            const uint4* __restrict__ Ap =
                hp_base + (size_t)((s + 1) & 1) * 16384 + rg * 32 + lane;

            uint4 abuf[4];
#pragma unroll
            for (int i = 0; i < 4; i++) abuf[i] = Ap[i * 256];

#pragma unroll 4
            for (int k8 = 0; k8 < 64; k8++) {
                uint4 av = abuf[k8 & 3];
                if (k8 < 60) abuf[k8 & 3] = Ap[(size_t)(k8 + 4) * 256];
                uint4 bv = *(const uint4*)&Bp[(k8 * 2 + wjq) * 128 + lane * 4];
                mma_tf32(acc0, (const unsigned*)&av, (const unsigned*)&bv.x);
                mma_tf32(acc1, (const unsigned*)&av, (const unsigned*)&bv.z);
            }
        }

        // ---- activations + cell update (all 4 gates local) ----
        float hval[2];
#pragma unroll
        for (int rr = 0; rr < 2; rr++) {
            float gi = acc0[rr * 2]     + xv[0][rr];
            float gf = acc0[rr * 2 + 1] + xv[1][rr];
            float gg = acc1[rr * 2]     + xv[2][rr];
            float go = acc1[rr * 2 + 1] + xv[3][rr];
            float i_ = 1.f / (1.f + expf(-gi));
            float f_ = 1.f / (1.f + expf(-gf));
            float G_ = tanhf(gg);
            float o_ = 1.f / (1.f + expf(-go));
            float cn = f_ * creg[rr] + i_ * G_;
            creg[rr] = cn;
            hval[rr] = o_ * tanhf(cn);
        }

        // fragment-major tf32 h first (on the critical path for the next step)
        {
            unsigned* wp = (unsigned*)(hp_base + (size_t)(s & 1) * 16384);
            uint2 hv2 = make_uint2(f2tf32(hval[0]), f2tf32(hval[1]));
            *(uint2*)(wp + woff) = hv2;
        }

        // fp32 h (layer output / next-layer GEMM input; not step-critical)
#pragma unroll
        for (int rr = 0; rr < 2; rr++)
            hb[(size_t)(r0 + rr * 8) * bstride + (size_t)t * tstride + j] = hval[rr];

        // ---- per-direction grid barrier (128 CTAs), skip after last step ----
        if (s < TT - 1) {
            __syncthreads();
            if (tid == 0) {
                unsigned oldf = ld_acquire(&g_barflag[dir]);
                unsigned v = atom_add_release(&g_barcnt[dir], 1);
                if (v == 127) {
                    g_barcnt[dir] = 0;
                    st_release(&g_barflag[dir], oldf + 1);
                } else {
                    while (ld_acquire(&g_barflag[dir]) == oldf) { }
                }
            }
            __syncthreads();
        }
    }
}

// ---------------- host orchestration ----------------------------------------
extern "C" void kernel_launch(void* const* d_in, const int* in_sizes, int n_in,
                              void* d_out, int out_size)
{
    const float* x  = (const float*)d_in[0];   // [128,256,512]
    const float* Wx = (const float*)d_in[1];   // [2,2,512,2048]
    const float* Wh = (const float*)d_in[2];   // [2,2,512,2048]
    const float* bs = (const float*)d_in[3];   // [2,2,2048]
    float* out = (float*)d_out;                // [128,256,1024]

    float *xp_base, *hist_base;
    unsigned *ap_base, *bp_base;
    cudaGetSymbolAddress((void**)&xp_base,   g_xproj);
    cudaGetSymbolAddress((void**)&hist_base, g_hist);
    cudaGetSymbolAddress((void**)&ap_base,   g_apack);
    cudaGetSymbolAddress((void**)&bp_base,   g_bpack);

    float* xp[2]   = { xp_base,   xp_base   + (size_t)BB * TT * G4 };
    float* hist[2] = { hist_base, hist_base + (size_t)BB * TT * HH };
    unsigned* ap[2] = { ap_base, ap_base + (size_t)64 * 2048 * 128 };

    const size_t WSTRIDE = (size_t)HH * G4;          // floats per (l,d) matrix
    const size_t BPSTRIDE = (size_t)64 * 256 * 64;   // words per packed B

    cudaFuncSetAttribute(lstm_rec, cudaFuncAttributeMaxDynamicSharedMemorySize,
                         REC_SMEM);

    const dim3 ggrid(16, 256);
    const dim3 agrid(64, 256);
    const dim3 rgrid(64, 2, 2);

    // ---- pack all 4 Wx matrices (one-shot, fragment-major) ----
    pack_b<<<dim3(64, 32, 4), 256>>>(Wx, bp_base);

    // ---- layer 0: pack x, run both direction projections ----
    pack_a<<<agrid, 256>>>(x, ap[0]);
    for (int d = 0; d < 2; d++)
        gemm_pk<<<ggrid, 256>>>(ap[0], bp_base + (size_t)d * BPSTRIDE,
                                bs + d * G4, xp[d]);

    // ---- layer 0 recurrence ----
    {
        RecP p;
        p.xp[0] = xp[0]; p.xp[1] = xp[1];
        p.Wh[0] = Wh;    p.Wh[1] = Wh + WSTRIDE;
        p.h[0]  = hist[0]; p.h[1] = hist[1];
        p.bstride = (long)TT * HH;
        p.tstride = HH;
        lstm_rec<<<rgrid, 256, REC_SMEM>>>(p);
    }

    // ---- layer 1: pack hidden histories, run projections ----
    pack_a<<<agrid, 256>>>(hist[0], ap[0]);
    pack_a<<<agrid, 256>>>(hist[1], ap[1]);
    for (int d = 0; d < 2; d++)
        gemm_pk<<<ggrid, 256>>>(ap[d], bp_base + (size_t)(2 + d) * BPSTRIDE,
                                bs + (2 + d) * G4, xp[d]);

    // ---- layer 1 recurrence (h lives directly in d_out) ----
    {
        RecP p;
        p.xp[0] = xp[0]; p.xp[1] = xp[1];
        p.Wh[0] = Wh + 2 * WSTRIDE; p.Wh[1] = Wh + 3 * WSTRIDE;
        p.h[0]  = out; p.h[1] = out + 512;
        p.bstride = (long)TT * 1024;
        p.tstride = 1024;
        lstm_rec<<<rgrid, 256, REC_SMEM>>>(p);
    }
}

// round 14
// speedup vs baseline: 1.5257x; 1.5257x over previous
#include <cuda_runtime.h>
#include <math.h>
#include <stdint.h>

#define BB 128
#define TT 256
#define HH 512
#define G4 2048  // 4*H

// ---------------- scratch (static device memory; no allocations) -------------
__device__ float    g_xproj[134217728];   // 2 dirs * 32768 * 2048 fp32 (512 MB)
__device__ float    g_hist[33554432];     // 2 dirs * 128*256*512 fp32 (128 MB)
__device__ unsigned g_apack[33554432];    // 2 packed A matrices (fragment-major) 128 MB
__device__ unsigned g_bpack[4194304];     // 4 packed Wx matrices (fragment-major) 16 MB
__device__ uint4    g_hpack[65536];       // rec h ping-pong: 2 dirs x 2 par x 16384 uint4 (1 MB)

// grid-barrier state (self-cleaning count; monotonically rising flag)
__device__ unsigned g_barcnt[2];
__device__ unsigned g_barflag[2];

// ---------------- tf32 helpers ----------------------------------------------
__device__ __forceinline__ unsigned f2tf32(float f) {
    unsigned r;
    asm("cvt.rna.tf32.f32 %0, %1;" : "=r"(r) : "f"(f));
    return r;
}

__device__ __forceinline__ void mma_tf32(float* c, const unsigned* a, const unsigned* b) {
    asm volatile(
        "mma.sync.aligned.m16n8k8.row.col.f32.tf32.tf32.f32 "
        "{%0,%1,%2,%3}, {%4,%5,%6,%7}, {%8,%9}, {%0,%1,%2,%3};"
        : "+f"(c[0]), "+f"(c[1]), "+f"(c[2]), "+f"(c[3])
        : "r"(a[0]), "r"(a[1]), "r"(a[2]), "r"(a[3]),
          "r"(b[0]), "r"(b[1]));
}

// ---------------- release/acquire primitives ---------------------------------
__device__ __forceinline__ unsigned atom_add_release(unsigned* p, unsigned v) {
    unsigned old;
    asm volatile("atom.release.gpu.global.add.u32 %0, [%1], %2;"
                 : "=r"(old) : "l"(p), "r"(v) : "memory");
    return old;
}
__device__ __forceinline__ void st_release(unsigned* p, unsigned v) {
    asm volatile("st.release.gpu.global.u32 [%0], %1;" :: "l"(p), "r"(v) : "memory");
}
__device__ __forceinline__ unsigned ld_acquire(unsigned* p) {
    unsigned v;
    asm volatile("ld.acquire.gpu.global.u32 %0, [%1];" : "=r"(v) : "l"(p) : "memory");
    return v;
}

// ---------------- operand pack kernels (unchanged) ---------------------------
__global__ __launch_bounds__(256)
void pack_a(const float* __restrict__ A, unsigned* __restrict__ Ag)
{
    const int k8  = blockIdx.x;
    const int rg  = blockIdx.y * 8 + (threadIdx.x >> 5);
    const int lane = threadIdx.x & 31;
    const int g = lane >> 2, tig = lane & 3;
    const size_t r0 = (size_t)(rg * 16 + g) * 512;
    const size_t r1 = r0 + 8 * 512;
    const int c0 = k8 * 8 + tig;
    uint4 u;
    u.x = f2tf32(A[r0 + c0]);
    u.y = f2tf32(A[r1 + c0]);
    u.z = f2tf32(A[r0 + c0 + 4]);
    u.w = f2tf32(A[r1 + c0 + 4]);
    *(uint4*)(Ag + ((size_t)k8 * 2048 + rg) * 128 + lane * 4) = u;
}

__global__ __launch_bounds__(256)
void pack_b(const float* __restrict__ Wx, unsigned* __restrict__ Bg)
{
    const int k8 = blockIdx.x;
    const int n8 = blockIdx.y * 8 + (threadIdx.x >> 5);
    const int ld = blockIdx.z;
    const int lane = threadIdx.x & 31;
    const int g = lane >> 2, tig = lane & 3;
    const float* W = Wx + (size_t)ld * 512 * 2048;
    const size_t col = (size_t)n8 * 8 + g;
    uint2 u;
    u.x = f2tf32(W[(size_t)(k8 * 8 + tig)     * 2048 + col]);
    u.y = f2tf32(W[(size_t)(k8 * 8 + tig + 4) * 2048 + col]);
    *(uint2*)(Bg + (((size_t)ld * 64 + k8) * 256 + n8) * 64 + lane * 2) = u;
}

// ---------------- zero-smem packed-fragment GEMM (unchanged) -----------------
__global__ __launch_bounds__(256)
void gemm_pk(const unsigned* __restrict__ Ag,
             const unsigned* __restrict__ Bg,
             const float* __restrict__ bias,
             float* __restrict__ C)
{
    const int tid  = threadIdx.x;
    const int wid  = tid >> 5;
    const int lane = tid & 31;
    const int g    = lane >> 2;
    const int tig  = lane & 3;
    const int wm   = wid >> 2;
    const int wn   = wid & 3;
    const long m0  = (long)blockIdx.y * 128;
    const int  n0  = blockIdx.x * 128;
    const int  rgb = blockIdx.y * 8 + wm * 4;
    const int  n8b = blockIdx.x * 16 + wn * 4;

    const uint4* __restrict__ A4 = (const uint4*)Ag;
    const uint2* __restrict__ B2 = (const uint2*)Bg;

    float acc[4][4][4];
#pragma unroll
    for (int i = 0; i < 4; i++)
#pragma unroll
        for (int j = 0; j < 4; j++)
#pragma unroll
            for (int q = 0; q < 4; q++) acc[i][j][q] = 0.f;

    uint4 av[4]; uint2 bv[4];
#pragma unroll
    for (int mt = 0; mt < 4; mt++)
        av[mt] = A4[(size_t)(rgb + mt) * 32 + lane];
#pragma unroll
    for (int nt = 0; nt < 4; nt++)
        bv[nt] = B2[(size_t)(n8b + nt) * 32 + lane];

#pragma unroll 4
    for (int k8 = 0; k8 < 64; k8++) {
        uint4 an[4]; uint2 bn[4];
        if (k8 < 63) {
            const size_t ao = (size_t)(k8 + 1) * 65536;
            const size_t bo = (size_t)(k8 + 1) * 8192;
#pragma unroll
            for (int mt = 0; mt < 4; mt++)
                an[mt] = A4[ao + (size_t)(rgb + mt) * 32 + lane];
#pragma unroll
            for (int nt = 0; nt < 4; nt++)
                bn[nt] = B2[bo + (size_t)(n8b + nt) * 32 + lane];
        }
#pragma unroll
        for (int mt = 0; mt < 4; mt++)
#pragma unroll
            for (int nt = 0; nt < 4; nt++)
                mma_tf32(acc[mt][nt], (const unsigned*)&av[mt],
                         (const unsigned*)&bv[nt]);
        if (k8 < 63) {
#pragma unroll
            for (int mt = 0; mt < 4; mt++) av[mt] = an[mt];
#pragma unroll
            for (int nt = 0; nt < 4; nt++) bv[nt] = bn[nt];
        }
    }

#pragma unroll
    for (int mt = 0; mt < 4; mt++) {
#pragma unroll
        for (int nt = 0; nt < 4; nt++) {
            long r0 = m0 + wm * 64 + mt * 16 + g;
            int cc = n0 + wn * 32 + nt * 8 + tig * 2;
            float b0 = bias[cc], b1 = bias[cc + 1];
            C[r0 * 2048 + cc]           = acc[mt][nt][0] + b0;
            C[r0 * 2048 + cc + 1]       = acc[mt][nt][1] + b1;
            C[(r0 + 8) * 2048 + cc]     = acc[mt][nt][2] + b0;
            C[(r0 + 8) * 2048 + cc + 1] = acc[mt][nt][3] + b1;
        }
    }
}

// ---------------- recurrence (R11 base + deep prefetch + arrive-early) -------
// grid (32 j-tiles, 2 M-halves, 2 dirs) = 128 CTAs, 512 threads, 1/SM.
// Thread owns (r0, r0+8) x one j with all 4 gates local (gate-interleaved B).
// A operand = packed tf32 h ping-pong, 8-deep register prefetch (covers L2 lat).
// Barrier: publish packed h -> release-arrive EARLY; fp32 h store and next-step
// xproj prefetch happen after arrive, off the inter-CTA critical path.
struct RecP {
    const float* xp[2];   // per dir input projections [B*T, 2048]
    const float* Wh[2];   // per dir [512, 2048]
    float*       h[2];    // per dir fp32 h base
    long bstride;
    long tstride;
};

#define REC_SMEM (64 * 4 * 128 * 4)   // Bp: [k8][wjq(4)][128 words] = 128 KB

__global__ __launch_bounds__(512)
void lstm_rec(RecP p)
{
    extern __shared__ unsigned Bp[];

    const int q    = blockIdx.x;        // j-tile: j in [q*16, q*16+16)
    const int mh   = blockIdx.y;        // M half: rows [mh*64, mh*64+64)
    const int dir  = blockIdx.z;
    const int tid  = threadIdx.x;
    const int wid  = tid >> 5;
    const int lane = tid & 31;
    const int g    = lane >> 2;
    const int tig  = lane & 3;
    const int wm   = wid & 3;           // M-group within half
    const int wjq  = wid >> 2;          // j-quad 0..3

    const float* __restrict__ xp = p.xp[dir];
    const float* __restrict__ Wh = p.Wh[dir];
    float* __restrict__ hb = p.h[dir];
    const long bstride = p.bstride;
    const long tstride = p.tstride;

    // base flag value, read before any arrival in this launch is possible
    const unsigned flag0 = ld_acquire(&g_barflag[dir]);

    // ---- pack Wh gate-interleaved fragments into smem (one-time) ----
#pragma unroll
    for (int i = 0; i < 4; i++) {
        const int k8 = wid * 4 + i;
#pragma unroll
        for (int wj = 0; wj < 4; wj++) {
#pragma unroll
            for (int gp = 0; gp < 2; gp++) {
                const size_t col = (size_t)(gp * 2 + (g & 1)) * 512
                                 + q * 16 + wj * 4 + (g >> 1);
                unsigned v0 = f2tf32(Wh[(size_t)(k8 * 8 + tig)     * 2048 + col]);
                unsigned v1 = f2tf32(Wh[(size_t)(k8 * 8 + tig + 4) * 2048 + col]);
                Bp[(k8 * 4 + wj) * 128 + lane * 4 + gp * 2]     = v0;
                Bp[(k8 * 4 + wj) * 128 + lane * 4 + gp * 2 + 1] = v1;
            }
        }
    }
    __syncthreads();

    const int r0 = mh * 64 + wm * 16 + g;       // batch rows r0, r0+8
    const int j  = q * 16 + wjq * 4 + tig;      // this thread's hidden unit
    const int rg = mh * 4 + wm;                  // packed-h rowgroup

    uint4* hp_base = g_hpack + (size_t)dir * 32768;
    const int k8p  = j >> 3;
    const int kbit = (j >> 2) & 1;
    const size_t woff = ((size_t)(k8p * 8 + rg)) * 128 + lane * 4 + kbit * 2;

    float creg[2] = {0.f, 0.f};

    // prefetch xproj gates for step 0
    float xv[4][2];
    {
        const int t0 = dir ? (TT - 1) : 0;
#pragma unroll
        for (int rr = 0; rr < 2; rr++) {
            const size_t xb = ((size_t)(r0 + rr * 8) * TT + t0) * 2048 + j;
#pragma unroll
            for (int gt = 0; gt < 4; gt++)
                xv[gt][rr] = xp[xb + gt * 512];
        }
    }

    for (int s = 0; s < TT; s++) {
        const int t = dir ? (TT - 1 - s) : s;

        float acc0[4] = {0.f, 0.f, 0.f, 0.f};   // gates i,f
        float acc1[4] = {0.f, 0.f, 0.f, 0.f};   // gates g,o

        if (s > 0) {
            // ---- wait for barrier of step s-1 (absolute target, wrap-safe) ----
            if (tid == 0) {
                while ((int)(ld_acquire(&g_barflag[dir]) - (flag0 + s)) < 0) { }
            }
            __syncthreads();

            const uint4* __restrict__ Ap =
                hp_base + (size_t)((s + 1) & 1) * 16384 + rg * 32 + lane;

            // 8-deep register prefetch covers ~250-cyc L2 latency
            uint4 abuf[8];
#pragma unroll
            for (int i = 0; i < 8; i++) abuf[i] = Ap[i * 256];

#pragma unroll 8
            for (int k8 = 0; k8 < 64; k8++) {
                uint4 av = abuf[k8 & 7];
                if (k8 < 56) abuf[k8 & 7] = Ap[(size_t)(k8 + 8) * 256];
                uint4 bv = *(const uint4*)&Bp[(k8 * 4 + wjq) * 128 + lane * 4];
                mma_tf32(acc0, (const unsigned*)&av, (const unsigned*)&bv.x);
                mma_tf32(acc1, (const unsigned*)&av, (const unsigned*)&bv.z);
            }
        }

        // ---- activations + cell update (all 4 gates local) ----
        float hval[2];
#pragma unroll
        for (int rr = 0; rr < 2; rr++) {
            float gi = acc0[rr * 2]     + xv[0][rr];
            float gf = acc0[rr * 2 + 1] + xv[1][rr];
            float gg = acc1[rr * 2]     + xv[2][rr];
            float go = acc1[rr * 2 + 1] + xv[3][rr];
            float i_ = 1.f / (1.f + expf(-gi));
            float f_ = 1.f / (1.f + expf(-gf));
            float G_ = tanhf(gg);
            float o_ = 1.f / (1.f + expf(-go));
            float cn = f_ * creg[rr] + i_ * G_;
            creg[rr] = cn;
            hval[rr] = o_ * tanhf(cn);
        }

        // publish packed tf32 h (critical for next step), then arrive EARLY
        {
            unsigned* wp = (unsigned*)(hp_base + (size_t)(s & 1) * 16384);
            *(uint2*)(wp + woff) = make_uint2(f2tf32(hval[0]), f2tf32(hval[1]));
        }

        if (s < TT - 1) {
            __syncthreads();              // all packed stores done (CTA scope)
            if (tid == 0) {
                unsigned v = atom_add_release(&g_barcnt[dir], 1);
                if (v == 63) {
                    g_barcnt[dir] = 0;
                    st_release(&g_barflag[dir], flag0 + s + 1);
                }
            }
            // ---- off-critical-path work below (after arrive) ----
        }

        // fp32 h store (layer output / next-layer GEMM input)
#pragma unroll
        for (int rr = 0; rr < 2; rr++)
            hb[(size_t)(r0 + rr * 8) * bstride + (size_t)t * tstride + j] = hval[rr];

        // prefetch xproj gates for step s+1 (depends only on t, not on h)
        if (s < TT - 1) {
            const int tn = dir ? (TT - 2 - s) : (s + 1);
#pragma unroll
            for (int rr = 0; rr < 2; rr++) {
                const size_t xb = ((size_t)(r0 + rr * 8) * TT + tn) * 2048 + j;
#pragma unroll
                for (int gt = 0; gt < 4; gt++)
                    xv[gt][rr] = xp[xb + gt * 512];
            }
        }
    }
}

// ---------------- host orchestration ----------------------------------------
extern "C" void kernel_launch(void* const* d_in, const int* in_sizes, int n_in,
                              void* d_out, int out_size)
{
    const float* x  = (const float*)d_in[0];   // [128,256,512]
    const float* Wx = (const float*)d_in[1];   // [2,2,512,2048]
    const float* Wh = (const float*)d_in[2];   // [2,2,512,2048]
    const float* bs = (const float*)d_in[3];   // [2,2,2048]
    float* out = (float*)d_out;                // [128,256,1024]

    float *xp_base, *hist_base;
    unsigned *ap_base, *bp_base;
    cudaGetSymbolAddress((void**)&xp_base,   g_xproj);
    cudaGetSymbolAddress((void**)&hist_base, g_hist);
    cudaGetSymbolAddress((void**)&ap_base,   g_apack);
    cudaGetSymbolAddress((void**)&bp_base,   g_bpack);

    float* xp[2]   = { xp_base,   xp_base   + (size_t)BB * TT * G4 };
    float* hist[2] = { hist_base, hist_base + (size_t)BB * TT * HH };
    unsigned* ap[2] = { ap_base, ap_base + (size_t)64 * 2048 * 128 };

    const size_t WSTRIDE = (size_t)HH * G4;          // floats per (l,d) matrix
    const size_t BPSTRIDE = (size_t)64 * 256 * 64;   // words per packed B

    cudaFuncSetAttribute(lstm_rec, cudaFuncAttributeMaxDynamicSharedMemorySize,
                         REC_SMEM);

    const dim3 ggrid(16, 256);
    const dim3 agrid(64, 256);
    const dim3 rgrid(32, 2, 2);

    // ---- pack all 4 Wx matrices (one-shot, fragment-major) ----
    pack_b<<<dim3(64, 32, 4), 256>>>(Wx, bp_base);

    // ---- layer 0: pack x, run both direction projections ----
    pack_a<<<agrid, 256>>>(x, ap[0]);
    for (int d = 0; d < 2; d++)
        gemm_pk<<<ggrid, 256>>>(ap[0], bp_base + (size_t)d * BPSTRIDE,
                                bs + d * G4, xp[d]);

    // ---- layer 0 recurrence ----
    {
        RecP p;
        p.xp[0] = xp[0]; p.xp[1] = xp[1];
        p.Wh[0] = Wh;    p.Wh[1] = Wh + WSTRIDE;
        p.h[0]  = hist[0]; p.h[1] = hist[1];
        p.bstride = (long)TT * HH;
        p.tstride = HH;
        lstm_rec<<<rgrid, 512, REC_SMEM>>>(p);
    }

    // ---- layer 1: pack hidden histories, run projections ----
    pack_a<<<agrid, 256>>>(hist[0], ap[0]);
    pack_a<<<agrid, 256>>>(hist[1], ap[1]);
    for (int d = 0; d < 2; d++)
        gemm_pk<<<ggrid, 256>>>(ap[d], bp_base + (size_t)(2 + d) * BPSTRIDE,
                                bs + (2 + d) * G4, xp[d]);

    // ---- layer 1 recurrence (h lives directly in d_out) ----
    {
        RecP p;
        p.xp[0] = xp[0]; p.xp[1] = xp[1];
        p.Wh[0] = Wh + 2 * WSTRIDE; p.Wh[1] = Wh + 3 * WSTRIDE;
        p.h[0]  = out; p.h[1] = out + 512;
        p.bstride = (long)TT * 1024;
        p.tstride = 1024;
        lstm_rec<<<rgrid, 512, REC_SMEM>>>(p);
    }
}